// round 5
// baseline (speedup 1.0000x reference)
#include <cuda_runtime.h>
#include <cuda_fp16.h>
#include <cstdint>

#define N_NODES    100000
#define EMB_DIM    128
#define BATCH      16384
#define NUM_SAMPLE 25

// fp16 shadow table: 100000 x 128 halfs = 25.6 MB (static device global; no runtime alloc)
__device__ __half g_emb_h[(size_t)N_NODES * EMB_DIM];

// ---------------- conversion: fp32 table -> fp16 shadow ----------------
// Each thread converts 8 floats (two float4 reads -> one uint4 store).
__global__ __launch_bounds__(256) void convert_kernel(const float4* __restrict__ emb)
{
    const int n = N_NODES * EMB_DIM / 8;   // 1,600,000
    int i = blockIdx.x * blockDim.x + threadIdx.x;
    if (i >= n) return;

    float4 a = __ldg(&emb[2 * i]);
    float4 b = __ldg(&emb[2 * i + 1]);

    __half2 h0 = __float22half2_rn(make_float2(a.x, a.y));
    __half2 h1 = __float22half2_rn(make_float2(a.z, a.w));
    __half2 h2 = __float22half2_rn(make_float2(b.x, b.y));
    __half2 h3 = __float22half2_rn(make_float2(b.z, b.w));

    uint4 o;
    o.x = *reinterpret_cast<unsigned int*>(&h0);
    o.y = *reinterpret_cast<unsigned int*>(&h1);
    o.z = *reinterpret_cast<unsigned int*>(&h2);
    o.w = *reinterpret_cast<unsigned int*>(&h3);
    reinterpret_cast<uint4*>(g_emb_h)[i] = o;
}

// ---------------- gather-mean over fp16 rows ----------------
// One warp per output row; lane l owns dims [4l, 4l+4) = one uint2 (4 halfs) per row.
__global__ __launch_bounds__(256) void gather_kernel(
    const int* __restrict__ neigh,   // [BATCH, NUM_SAMPLE] int32
    float4* __restrict__ out)        // [BATCH, 32] as float4
{
    const int warp_id = (blockIdx.x * blockDim.x + threadIdx.x) >> 5;
    const int lane    = threadIdx.x & 31;
    if (warp_id >= BATCH) return;

    const uint2* embh = reinterpret_cast<const uint2*>(g_emb_h); // row stride = 32 uint2

    const int* nb = neigh + warp_id * NUM_SAMPLE;
    int my_idx = (lane < NUM_SAMPLE) ? nb[lane] : 0;

    float ax = 0.f, ay = 0.f, az = 0.f, aw = 0.f;

    #pragma unroll
    for (int s = 0; s < NUM_SAMPLE; ++s) {
        int id = __shfl_sync(0xffffffffu, my_idx, s);
        uint2 u = __ldg(&embh[(unsigned)id * 32u + lane]);
        __half2 h0 = *reinterpret_cast<__half2*>(&u.x);
        __half2 h1 = *reinterpret_cast<__half2*>(&u.y);
        float2 f0 = __half22float2(h0);
        float2 f1 = __half22float2(h1);
        ax += f0.x; ay += f0.y; az += f1.x; aw += f1.y;
    }

    const float inv = 1.0f / (float)NUM_SAMPLE;
    out[(unsigned)warp_id * 32u + lane] = make_float4(ax * inv, ay * inv, az * inv, aw * inv);
}

extern "C" void kernel_launch(void* const* d_in, const int* in_sizes, int n_in,
                              void* d_out, int out_size)
{
    const float4* emb   = (const float4*)d_in[0];
    const int*    neigh = (const int*)d_in[1];
    float4*       out   = (float4*)d_out;

    // Kernel 1: fp32 -> fp16 shadow table (must rerun every launch; same stream
    // ordering guarantees the gather sees the converted table).
    const int n_conv = N_NODES * EMB_DIM / 8;
    convert_kernel<<<(n_conv + 255) / 256, 256>>>(emb);

    // Kernel 2: gather-mean. One warp per row, 8 warps per block.
    const int threads = 256;
    const int blocks  = (BATCH + (threads / 32) - 1) / (threads / 32);
    gather_kernel<<<blocks, threads>>>(neigh, out);
}

// round 6
// speedup vs baseline: 1.0828x; 1.0828x over previous
#include <cuda_runtime.h>
#include <cstdint>

#define N_NODES    100000
#define EMB_DIM    128
#define BATCH      16384
#define NUM_SAMPLE 25

#define VEC_PER_ROW (EMB_DIM / 4)   // 32 float4 per row

// Persistent single-wave launch: 148 SMs x 8 CTAs of 256 threads.
#define GRID_BLOCKS 1184
#define BLOCK_THREADS 256
#define WARPS_TOTAL (GRID_BLOCKS * BLOCK_THREADS / 32)   // 9472 warps

__global__ __launch_bounds__(BLOCK_THREADS) void mean_agg_kernel(
    const float4* __restrict__ emb,      // [N_NODES, 32] as float4
    const int* __restrict__ neigh,       // [BATCH, NUM_SAMPLE], int32
    float4* __restrict__ out)            // [BATCH, 32] as float4
{
    const int warp_base = (blockIdx.x * BLOCK_THREADS + threadIdx.x) >> 5;
    const int lane      = threadIdx.x & 31;
    const float inv     = 1.0f / (float)NUM_SAMPLE;   // 0.04

    // Grid-stride over rows: 16384 rows / 9472 warps -> 1..2 rows per warp,
    // single wave, no wave-transition bubble.
    for (int row = warp_base; row < BATCH; row += WARPS_TOTAL) {
        const int* nb = neigh + row * NUM_SAMPLE;
        int my_idx = (lane < NUM_SAMPLE) ? nb[lane] : 0;

        float4 acc = make_float4(0.f, 0.f, 0.f, 0.f);

        #pragma unroll
        for (int s = 0; s < NUM_SAMPLE; ++s) {
            int id = __shfl_sync(0xffffffffu, my_idx, s);
            float4 v = __ldg(&emb[(unsigned)id * VEC_PER_ROW + lane]);
            acc.x += v.x;
            acc.y += v.y;
            acc.z += v.z;
            acc.w += v.w;
        }

        acc.x *= inv; acc.y *= inv; acc.z *= inv; acc.w *= inv;
        out[(unsigned)row * VEC_PER_ROW + lane] = acc;
    }
}

extern "C" void kernel_launch(void* const* d_in, const int* in_sizes, int n_in,
                              void* d_out, int out_size)
{
    const float4* emb   = (const float4*)d_in[0];
    const int*    neigh = (const int*)d_in[1];
    float4*       out   = (float4*)d_out;

    mean_agg_kernel<<<GRID_BLOCKS, BLOCK_THREADS>>>(emb, neigh, out);
}